// round 13
// baseline (speedup 1.0000x reference)
#include <cuda_runtime.h>

// cumprod along dim 1 of a (4096, 8192) fp32 matrix.
// R8 winner core + STATIC persistent loop (tail removal only; no atomics,
// no extra register buffers). Grid = 740 (5 CTAs/SM x 148 SMs); CTA b
// processes rows b, b+740, ... Per row: 8 warps, warp w owns floats
// [1024w, 1024w+1024), lane L owns float4 L of each 128-float chunk
// (coalesced LDG/STG.128), values register-resident end-to-end, early
// order-independent segment totals, ONE barrier per row with parity-
// double-buffered wtot (fast warps touch only the opposite parity slot).

#define ROW_LEN  8192
#define NROWS    4096
#define THREADS  256
#define NWARPS   8
#define CHUNKS   8                    // 128-float chunks per warp segment
#define SEG_VEC  256                  // float4 per warp segment
#define GRID     740                  // 5 CTAs/SM * 148 SMs

__global__ void __launch_bounds__(THREADS, 5)
cumprod_dim1_kernel(const float* __restrict__ x, float* __restrict__ y) {
    __shared__ float wtot[2][NWARPS];

    const int t    = threadIdx.x;
    const int lane = t & 31;
    const int w    = t >> 5;
    const int segl = w * SEG_VEC + lane;   // lane's float4 slot in chunk 0

    int p = 0;
    for (int r = blockIdx.x; r < NROWS; r += GRID, p ^= 1) {
        const size_t row_off = (size_t)r * ROW_LEN;
        const float4* __restrict__ xin  = reinterpret_cast<const float4*>(x + row_off);
        float4* __restrict__       yout = reinterpret_cast<float4*>(y + row_off);

        // ---- front-batched loads: 8 LDG.128 in flight per warp ----
        float4 vals[CHUNKS];
        #pragma unroll
        for (int c = 0; c < CHUNKS; c++)
            vals[c] = __ldcs(&xin[segl + c * 32]);

        // ---- EARLY segment total: order-independent tree product ----
        float tp = 1.0f;
        #pragma unroll
        for (int c = 0; c < CHUNKS; c++) {
            float4 v = vals[c];
            tp *= (v.x * v.y) * (v.z * v.w);
        }
        #pragma unroll
        for (int o = 1; o < 32; o <<= 1)
            tp *= __shfl_xor_sync(0xffffffffu, tp, o);
        if (lane == 0) wtot[p][w] = tp;
        __syncthreads();                  // one barrier per row (parity slots)

        // ---- cross-warp exclusive prefix folded into the running carry ----
        float carry = 1.0f;
        #pragma unroll
        for (int ww = 0; ww < NWARPS - 1; ww++) {
            float wt = wtot[p][ww];
            if (ww < w) carry *= wt;
        }

        // ---- scan + scale + store, single pass ----
        #pragma unroll
        for (int c = 0; c < CHUNKS; c++) {
            float4 v = vals[c];
            v.y *= v.x;
            v.z *= v.y;
            v.w *= v.z;

            float s = v.w;
            #pragma unroll
            for (int o = 1; o < 32; o <<= 1) {
                float tv = __shfl_up_sync(0xffffffffu, s, o);
                if (lane >= o) s *= tv;
            }
            float e   = __shfl_up_sync(0xffffffffu, s, 1);
            if (lane == 0) e = 1.0f;
            float tot = __shfl_sync(0xffffffffu, s, 31);

            const float ce = carry * e;
            v.x *= ce; v.y *= ce; v.z *= ce; v.w *= ce;
            __stcs(&yout[segl + c * 32], v);

            carry *= tot;
        }
    }
}

extern "C" void kernel_launch(void* const* d_in, const int* in_sizes, int n_in,
                              void* d_out, int out_size) {
    const float* x = (const float*)d_in[0];
    float* y = (float*)d_out;
    cumprod_dim1_kernel<<<GRID, THREADS>>>(x, y);
}

// round 14
// speedup vs baseline: 1.1309x; 1.1309x over previous
#include <cuda_runtime.h>

// cumprod along dim 1 of a (4096, 8192) fp32 matrix.  [FINAL — R8 champion]
// CTA-per-row, 256 threads = 8 warps. Warp w owns floats [1024w, 1024w+1024);
// lane L owns float4 L of each 128-float chunk -> loads AND stores natively
// coalesced, values register-resident end-to-end. Segment totals are computed
// EARLY (order-independent tree product + butterfly reduce), so the barrier
// fires right after the loads; the scan+scale+store pass runs after it with
// the cross-warp prefix already folded into the carry.
//
// Why stop optimizing: total L2 traffic (read-fill + write) is 268 MB in
// ~35 us = ~7.6 TB/s, which sits AT the B300 LTS full-chip throughput cap
// (~6300 B/cyc, path-independent). All 13 structural variants (occupancy
// 33-87%, MLP 2-16, smem-staged / register-resident / two-pass / persistent)
// plateau at 5.4-6.0 TB/s DRAM against this same ceiling; this shape is the
// fastest measured (43.8 us bench, 35.3 us kernel, 75.7% DRAM).

#define ROW_LEN  8192
#define THREADS  256
#define NWARPS   8
#define CHUNKS   8                    // 128-float chunks per warp segment
#define SEG_VEC  256                  // float4 per warp segment

__global__ void __launch_bounds__(THREADS, 5)
cumprod_dim1_kernel(const float* __restrict__ x, float* __restrict__ y) {
    __shared__ float wtot[NWARPS];

    const int t    = threadIdx.x;
    const int lane = t & 31;
    const int w    = t >> 5;

    const size_t row_off = (size_t)blockIdx.x * ROW_LEN;
    const float4* __restrict__ xin  = reinterpret_cast<const float4*>(x + row_off);
    float4* __restrict__       yout = reinterpret_cast<float4*>(y + row_off);

    const int seg = w * SEG_VEC;      // float4 base of this warp's segment

    // ---- front-batched loads: 8 LDG.128 in flight ----
    float4 vals[CHUNKS];
    #pragma unroll
    for (int c = 0; c < CHUNKS; c++)
        vals[c] = __ldcs(&xin[seg + c * 32 + lane]);

    // ---- EARLY segment total: order-independent tree product ----
    float tp = 1.0f;
    #pragma unroll
    for (int c = 0; c < CHUNKS; c++) {
        float4 v = vals[c];
        tp *= (v.x * v.y) * (v.z * v.w);
    }
    #pragma unroll
    for (int o = 1; o < 32; o <<= 1)
        tp *= __shfl_xor_sync(0xffffffffu, tp, o);
    if (lane == 0) wtot[w] = tp;
    __syncthreads();

    // ---- cross-warp exclusive prefix, folded into the running carry ----
    float carry = 1.0f;
    #pragma unroll
    for (int ww = 0; ww < NWARPS - 1; ww++) {
        float wt = wtot[ww];
        if (ww < w) carry *= wt;
    }

    // ---- scan + scale + store, single pass ----
    #pragma unroll
    for (int c = 0; c < CHUNKS; c++) {
        float4 v = vals[c];
        // local inclusive prefix within the thread's 4 elements
        v.y *= v.x;
        v.z *= v.y;
        v.w *= v.z;

        // warp inclusive scan (product) of per-thread totals
        float s = v.w;
        #pragma unroll
        for (int o = 1; o < 32; o <<= 1) {
            float tv = __shfl_up_sync(0xffffffffu, s, o);
            if (lane >= o) s *= tv;
        }
        float e   = __shfl_up_sync(0xffffffffu, s, 1);
        if (lane == 0) e = 1.0f;
        float tot = __shfl_sync(0xffffffffu, s, 31);

        const float ce = carry * e;   // global exclusive prefix for this thread
        v.x *= ce; v.y *= ce; v.z *= ce; v.w *= ce;
        __stcs(&yout[seg + c * 32 + lane], v);

        carry *= tot;
    }
}

extern "C" void kernel_launch(void* const* d_in, const int* in_sizes, int n_in,
                              void* d_out, int out_size) {
    const float* x = (const float*)d_in[0];
    float* y = (float*)d_out;
    const int rows = in_sizes[0] / ROW_LEN;   // 4096
    cumprod_dim1_kernel<<<rows, THREADS>>>(x, y);
}